// round 10
// baseline (speedup 1.0000x reference)
#include <cuda_runtime.h>
#include <cstdint>

// DCNv2 (R10): tensor-core einsum, traffic-fixed.
// out[16, px] = W[16x27] @ S[27, px] per (b,g); S from constant-shift bilinear
// sampling. mma.sync.m16n8k8.tf32, split-tf32 (Wh*Sh + Wh*Sl + Wl*Sh) with
// hi/lo computed in registers (S stored raw fp32), conflict-free S pitch,
// 3 independent accumulator chains. CTA = 32x8 px, 256 thr, 46.9KB smem.

namespace {
constexpr int Hdim = 160;
constexpr int Wdim = 160;
constexpr int TX = 32;                  // tile cols
constexpr int TY = 8;                  // tile rows
constexpr int HALO = 5;                 // shifts provably in [-4,4], +1 corner
constexpr int SMW = TX + 2 * HALO;      // 42
constexpr int SMH = TY + 2 * HALO;      // 18
constexpr int THREADS = 256;
constexpr int PXT = TX * TY;            // 256 px per tile
constexpr int SPITCH = 264;             // S row pitch in floats; 264 % 32 == 8
// smem layout (bytes)
constexpr int S_BYTES    = 32 * SPITCH * 4;          // 33792
constexpr int WH_OFF     = S_BYTES;                  // 16*32 floats
constexpr int WL_OFF     = WH_OFF + 16 * 32 * 4;     // 35840
constexpr int SMIN_OFF   = WL_OFF + 16 * 32 * 4;     // 37888
constexpr int SMEM_BYTES = SMIN_OFF + 3 * SMH * SMW * 4;   // 46960 < 48KB
}

__device__ __forceinline__ float tf32_rna(float x) {
    uint32_t u;
    asm("cvt.rna.tf32.f32 %0, %1;" : "=r"(u) : "f"(x));
    return __uint_as_float(u);
}

__device__ __forceinline__ void mma_tf32(float* c,
                                         uint32_t a0, uint32_t a1, uint32_t a2, uint32_t a3,
                                         uint32_t b0, uint32_t b1) {
    asm("mma.sync.aligned.m16n8k8.row.col.f32.tf32.tf32.f32 "
        "{%0,%1,%2,%3}, {%4,%5,%6,%7}, {%8,%9}, {%0,%1,%2,%3};"
        : "+f"(c[0]), "+f"(c[1]), "+f"(c[2]), "+f"(c[3])
        : "r"(a0), "r"(a1), "r"(a2), "r"(a3), "r"(b0), "r"(b1));
}

__global__ __launch_bounds__(THREADS, 3)
void dcn_kernel(const float* __restrict__ input,
                const float* __restrict__ weight,
                const float* __restrict__ offset,
                float* __restrict__ out)
{
    extern __shared__ char dsm[];
    float* S    = reinterpret_cast<float*>(dsm);            // [32][SPITCH] raw fp32
    float* Wh   = reinterpret_cast<float*>(dsm + WH_OFF);   // [16][32]
    float* Wl   = reinterpret_cast<float*>(dsm + WL_OFF);   // [16][32]
    float* smin = reinterpret_cast<float*>(dsm + SMIN_OFF); // [3][SMH][SMW]

    const int bg = blockIdx.z;          // 0..47
    const int b  = bg / 3;
    const int g  = bg % 3;
    const int tile_x = blockIdx.x * TX;
    const int tile_y = blockIdx.y * TY;
    const int tid = threadIdx.x;

    // ---- phase 0: weights (hi/lo split, zero-padded K=32) ----
    for (int i = tid; i < 16 * 32; i += THREADS) {
        const int o  = i >> 5;
        const int kk = i & 31;
        float w = 0.0f;
        if (kk < 27) {
            const int c = kk / 9, k = kk % 9;
            w = weight[k * 144 + (g * 16 + o) * 3 + c];
        }
        const float hi = tf32_rna(w);
        Wh[i] = hi;
        Wl[i] = w - hi;
    }
    // zero S rows 27..31 (read by MMA kb=3, never written by sampling)
    for (int i = tid; i < 5 * PXT; i += THREADS) {
        const int r = i >> 8, n = i & 255;
        S[(27 + r) * SPITCH + n] = 0.0f;
    }
    // stage input tile (+halo, zero pad outside image)
    const float* inb = input + (size_t)(b >> 1) * 9 * Hdim * Wdim
                             + (size_t)(g * 3) * Hdim * Wdim;
    for (int i = tid; i < 3 * SMH * SMW; i += THREADS) {
        const int c = i / (SMH * SMW);
        const int r = (i / SMW) % SMH;
        const int q = i % SMW;
        const int gy = tile_y + r - HALO;
        const int gx = tile_x + q - HALO;
        float v = 0.0f;
        if (gy >= 0 && gy < Hdim && gx >= 0 && gx < Wdim)
            v = inb[(size_t)c * Hdim * Wdim + gy * Wdim + gx];
        smin[i] = v;
    }

    // ---- shift constants (uniform across block) ----
    const float offy = __ldg(&offset[(b * 3 + g) * 2 + 0]);
    const float offx = __ldg(&offset[(b * 3 + g) * 2 + 1]);
    const float dyv = 1.0f + 3.0f / offy;   // |shift| for p = +-1; p=0 -> 0
    const float dxv = 1.0f + 3.0f / offx;
    const float fyMf = floorf(-dyv), fyPf = floorf(dyv);
    const float fxMf = floorf(-dxv), fxPf = floorf(dxv);
    const int fyM = (int)fyMf, fyP = (int)fyPf;
    const int fxM = (int)fxMf, fxP = (int)fxPf;
    const float wyM = -dyv - fyMf, wyP = dyv - fyPf;
    const float wxM = -dxv - fxMf, wxP = dxv - fxPf;

    __syncthreads();

    // ---- phase 1: sampling, 1 px/thread, store raw fp32 ----
    {
        const int x = tid & 31;
        const int y = tid >> 5;           // 0..7
        #pragma unroll
        for (int c = 0; c < 3; c++) {
            const float* Bc = smin + c * (SMH * SMW) + (y + HALO) * SMW + (x + HALO);
            const float* r0 = Bc + fyM * SMW;   // p_y=-1 rows
            const float* r1 = r0 + SMW;
            const float* q0 = Bc + fyP * SMW;   // p_y=+1 rows
            const float* q1 = q0 + SMW;

            #define HL(P, FX, WX) (fmaf((WX), (P)[(FX) + 1] - (P)[(FX)], (P)[(FX)]))
            #define VL(A, B2, W)  (fmaf((W), (B2) - (A), (A)))

            float* Sc = S + (c * 9) * SPITCH + tid;
            Sc[4 * SPITCH] = Bc[0];
            Sc[3 * SPITCH] = HL(Bc, fxM, wxM);
            Sc[5 * SPITCH] = HL(Bc, fxP, wxP);
            Sc[1 * SPITCH] = VL(r0[0], r1[0], wyM);
            Sc[0 * SPITCH] = VL(HL(r0, fxM, wxM), HL(r1, fxM, wxM), wyM);
            Sc[2 * SPITCH] = VL(HL(r0, fxP, wxP), HL(r1, fxP, wxP), wyM);
            Sc[7 * SPITCH] = VL(q0[0], q1[0], wyP);
            Sc[6 * SPITCH] = VL(HL(q0, fxM, wxM), HL(q1, fxM, wxM), wyP);
            Sc[8 * SPITCH] = VL(HL(q0, fxP, wxP), HL(q1, fxP, wxP), wyP);
            #undef HL
            #undef VL
        }
    }

    __syncthreads();

    // ---- phase 2: MMA. 8 warps x 4 n-blocks of 8 px; K = 32 (4 k-blocks) ----
    {
        const int lane = tid & 31;
        const int warp = tid >> 5;        // 0..7
        const int tig  = lane & 3;        // thread-in-group
        const int gid  = lane >> 2;       // group id (0..7)

        // A fragments (weights), loaded once (broadcast LDS)
        uint32_t ah[4][4], al[4][4];
        #pragma unroll
        for (int kb = 0; kb < 4; kb++) {
            const int kc0 = kb * 8 + tig;
            const int kc1 = kc0 + 4;
            ah[kb][0] = __float_as_uint(Wh[gid * 32 + kc0]);
            ah[kb][1] = __float_as_uint(Wh[(gid + 8) * 32 + kc0]);
            ah[kb][2] = __float_as_uint(Wh[gid * 32 + kc1]);
            ah[kb][3] = __float_as_uint(Wh[(gid + 8) * 32 + kc1]);
            al[kb][0] = __float_as_uint(Wl[gid * 32 + kc0]);
            al[kb][1] = __float_as_uint(Wl[(gid + 8) * 32 + kc0]);
            al[kb][2] = __float_as_uint(Wl[gid * 32 + kc1]);
            al[kb][3] = __float_as_uint(Wl[(gid + 8) * 32 + kc1]);
        }

        #pragma unroll 1
        for (int j = 0; j < 4; j++) {
            const int n0 = (warp * 4 + j) * 8;      // n-block base (0..248)
            float ch[4] = {0.f, 0.f, 0.f, 0.f};     // Wh * Sh
            float cm[4] = {0.f, 0.f, 0.f, 0.f};     // Wh * Sl
            float cl[4] = {0.f, 0.f, 0.f, 0.f};     // Wl * Sh
            #pragma unroll
            for (int kb = 0; kb < 4; kb++) {
                const float s0 = S[(kb * 8 + tig) * SPITCH + n0 + gid];
                const float s1 = S[(kb * 8 + tig + 4) * SPITCH + n0 + gid];
                const float h0 = tf32_rna(s0);
                const float h1 = tf32_rna(s1);
                const uint32_t b0h = __float_as_uint(h0);
                const uint32_t b1h = __float_as_uint(h1);
                const uint32_t b0l = __float_as_uint(s0 - h0);
                const uint32_t b1l = __float_as_uint(s1 - h1);
                mma_tf32(ch, ah[kb][0], ah[kb][1], ah[kb][2], ah[kb][3], b0h, b1h);
                mma_tf32(cm, ah[kb][0], ah[kb][1], ah[kb][2], ah[kb][3], b0l, b1l);
                mma_tf32(cl, al[kb][0], al[kb][1], al[kb][2], al[kb][3], b0h, b1h);
            }
            const float c0 = ch[0] + cm[0] + cl[0];
            const float c1 = ch[1] + cm[1] + cl[1];
            const float c2 = ch[2] + cm[2] + cl[2];
            const float c3 = ch[3] + cm[3] + cl[3];

            // store: px pair (n0+2*tig, +1) -> same output row
            const int px0 = n0 + 2 * tig;
            const int gy = tile_y + (px0 >> 5);
            const int gx = tile_x + (px0 & 31);
            float* base = out + (size_t)(b * 48 + g * 16 + gid) * (Hdim * Wdim)
                              + gy * Wdim + gx;
            *reinterpret_cast<float2*>(base) = make_float2(c0, c1);
            *reinterpret_cast<float2*>(base + (size_t)8 * Hdim * Wdim) = make_float2(c2, c3);
        }
    }
}

extern "C" void kernel_launch(void* const* d_in, const int* in_sizes, int n_in,
                              void* d_out, int out_size)
{
    const float* input  = (const float*)d_in[0];
    const float* weight = (const float*)d_in[1];
    const float* offset = (const float*)d_in[2];
    float* out = (float*)d_out;

    dim3 grid(Wdim / TX, Hdim / TY, 48);   // 5 x 20 x 48
    dcn_kernel<<<grid, THREADS, SMEM_BYTES>>>(input, weight, offset, out);
}

// round 14
// speedup vs baseline: 1.9265x; 1.9265x over previous
#include <cuda_runtime.h>
#include <cstdint>

// DCNv2 (R11, fourth submission; R11-R13 all hit broker GPUAcquisitionTimeout
// before launch): tensor-core einsum with fixed feeding.
// out[16, px] = W[16x27] @ S[27, px] per (b,g). Sampling 2 px/thread with
// shared corner rows; S raw fp32, 27 rows, XOR-16 swizzled (conflict-free
// STS + B-loads); weights [k][o] (conflict-light A-frags); split-tf32
// (Wh*Sh + Wh*Sl + Wl*Sh) m16n8k8 MMAs, hi/lo computed in registers.
// CTA = 16x16 px, 128 threads, 40.7KB smem (no attribute call), 5 CTAs/SM.

namespace {
constexpr int Hdim = 160;
constexpr int Wdim = 160;
constexpr int TX = 16;
constexpr int TY = 16;
constexpr int HALO = 5;                  // shifts provably in [-4,4], +1 corner
constexpr int SMW = TX + 2 * HALO;       // 26
constexpr int SMH = TY + 2 * HALO;       // 26
constexpr int THREADS = 128;
constexpr int SPITCH = 264;              // S col pitch (floats); 264 % 32 == 8
// smem layout (bytes)
constexpr int S_BYTES    = 27 * SPITCH * 4;              // 28512
constexpr int WH_OFF     = S_BYTES;                      // Wt_h[32][16]
constexpr int WL_OFF     = WH_OFF + 32 * 16 * 4;         // 30560
constexpr int SMIN_OFF   = WL_OFF + 32 * 16 * 4;         // 32608
constexpr int SMEM_BYTES = SMIN_OFF + 3 * SMH * SMW * 4; // 40720 < 48KB
}

__device__ __forceinline__ float tf32_rna(float x) {
    uint32_t u;
    asm("cvt.rna.tf32.f32 %0, %1;" : "=r"(u) : "f"(x));
    return __uint_as_float(u);
}

__device__ __forceinline__ void mma_tf32(float* c,
                                         uint32_t a0, uint32_t a1, uint32_t a2, uint32_t a3,
                                         uint32_t b0, uint32_t b1) {
    asm("mma.sync.aligned.m16n8k8.row.col.f32.tf32.tf32.f32 "
        "{%0,%1,%2,%3}, {%4,%5,%6,%7}, {%8,%9}, {%0,%1,%2,%3};"
        : "+f"(c[0]), "+f"(c[1]), "+f"(c[2]), "+f"(c[3])
        : "r"(a0), "r"(a1), "r"(a2), "r"(a3), "r"(b0), "r"(b1));
}

// XOR-16 swizzle on the S column index (bit5 -> flip bit4)
__device__ __forceinline__ int scol(int px) {
    return px ^ (((px >> 5) & 1) << 4);
}

__global__ __launch_bounds__(THREADS, 5)
void dcn_kernel(const float* __restrict__ input,
                const float* __restrict__ weight,
                const float* __restrict__ offset,
                float* __restrict__ out)
{
    extern __shared__ char dsm[];
    float* S    = reinterpret_cast<float*>(dsm);            // [27][SPITCH]
    float* Wth  = reinterpret_cast<float*>(dsm + WH_OFF);   // [32][16] (k-major)
    float* Wtl  = reinterpret_cast<float*>(dsm + WL_OFF);   // [32][16]
    float* smin = reinterpret_cast<float*>(dsm + SMIN_OFF); // [3][SMH][SMW]

    const int bg = blockIdx.z;          // 0..47
    const int b  = bg / 3;
    const int g  = bg % 3;
    const int tile_x = blockIdx.x * TX;
    const int tile_y = blockIdx.y * TY;
    const int tid = threadIdx.x;

    // ---- phase 0: weights (hi/lo split, k-major, zero rows 27..31) ----
    for (int i = tid; i < 32 * 16; i += THREADS) {
        const int kk = i >> 4;          // 0..31
        const int o  = i & 15;
        float w = 0.0f;
        if (kk < 27) {
            const int c = kk / 9, k = kk % 9;
            w = weight[k * 144 + (g * 16 + o) * 3 + c];
        }
        const float hi = tf32_rna(w);
        Wth[i] = hi;
        Wtl[i] = w - hi;
    }
    // stage input tile (+halo, zero pad outside image)
    const float* inb = input + (size_t)(b >> 1) * 9 * Hdim * Wdim
                             + (size_t)(g * 3) * Hdim * Wdim;
    for (int i = tid; i < 3 * SMH * SMW; i += THREADS) {
        const int c = i / (SMH * SMW);
        const int r = (i / SMW) % SMH;
        const int q = i % SMW;
        const int gy = tile_y + r - HALO;
        const int gx = tile_x + q - HALO;
        float v = 0.0f;
        if (gy >= 0 && gy < Hdim && gx >= 0 && gx < Wdim)
            v = inb[(size_t)c * Hdim * Wdim + gy * Wdim + gx];
        smin[i] = v;
    }

    // ---- shift constants (uniform across block) ----
    const float offy = __ldg(&offset[(b * 3 + g) * 2 + 0]);
    const float offx = __ldg(&offset[(b * 3 + g) * 2 + 1]);
    const float dyv = 1.0f + 3.0f / offy;   // |shift| for p = +-1; p=0 -> 0
    const float dxv = 1.0f + 3.0f / offx;
    const float fyMf = floorf(-dyv), fyPf = floorf(dyv);
    const float fxMf = floorf(-dxv), fxPf = floorf(dxv);
    const int fyM = (int)fyMf, fyP = (int)fyPf;
    const int fxM = (int)fxMf, fxP = (int)fxPf;
    const float wyM = -dyv - fyMf, wyP = dyv - fyPf;
    const float wxM = -dxv - fxMf, wxP = dxv - fxPf;

    __syncthreads();

    // ---- phase 1: sampling, 2 px/thread (1 col x 2 rows), shared lerps ----
    {
        const int x  = tid & 15;
        const int yh = tid >> 4;          // 0..7
        const int y0 = yh * 2;
        const int sc0 = scol(y0 * 16 + x);        // both px share bit5 parity
        const int sc1 = scol(y0 * 16 + 16 + x);

        #pragma unroll
        for (int c = 0; c < 3; c++) {
            const float* Bc = smin + c * (SMH * SMW) + (y0 + HALO) * SMW + (x + HALO);
            const float* BM = Bc + fyM * SMW;   // p_y=-1 rows
            const float* BP = Bc + fyP * SMW;   // p_y=+1 rows
            float* Sc = S + (c * 9) * SPITCH;

            #define HL(P, FX, WX) (fmaf((WX), (P)[(FX) + 1] - (P)[(FX)], (P)[(FX)]))
            #define VL(A, B2, W)  (fmaf((W), (B2) - (A), (A)))
            #define PUT(K, V0, V1) do { Sc[(K) * SPITCH + sc0] = (V0); \
                                        Sc[(K) * SPITCH + sc1] = (V1); } while (0)

            // p_y = 0
            PUT(4, Bc[0], Bc[SMW]);
            PUT(3, HL(Bc, fxM, wxM), HL(Bc + SMW, fxM, wxM));
            PUT(5, HL(Bc, fxP, wxP), HL(Bc + SMW, fxP, wxP));
            // p_y = -1 (3 shared rows for 2 px)
            {
                float v0 = BM[0], v1 = BM[SMW], v2 = BM[2 * SMW];
                PUT(1, VL(v0, v1, wyM), VL(v1, v2, wyM));
                float h0 = HL(BM, fxM, wxM), h1 = HL(BM + SMW, fxM, wxM),
                      h2 = HL(BM + 2 * SMW, fxM, wxM);
                PUT(0, VL(h0, h1, wyM), VL(h1, h2, wyM));
                float e0 = HL(BM, fxP, wxP), e1 = HL(BM + SMW, fxP, wxP),
                      e2 = HL(BM + 2 * SMW, fxP, wxP);
                PUT(2, VL(e0, e1, wyM), VL(e1, e2, wyM));
            }
            // p_y = +1
            {
                float v0 = BP[0], v1 = BP[SMW], v2 = BP[2 * SMW];
                PUT(7, VL(v0, v1, wyP), VL(v1, v2, wyP));
                float h0 = HL(BP, fxM, wxM), h1 = HL(BP + SMW, fxM, wxM),
                      h2 = HL(BP + 2 * SMW, fxM, wxM);
                PUT(6, VL(h0, h1, wyP), VL(h1, h2, wyP));
                float e0 = HL(BP, fxP, wxP), e1 = HL(BP + SMW, fxP, wxP),
                      e2 = HL(BP + 2 * SMW, fxP, wxP);
                PUT(8, VL(e0, e1, wyP), VL(e1, e2, wyP));
            }
            #undef HL
            #undef VL
            #undef PUT
        }
    }

    __syncthreads();

    // ---- phase 2: MMA. 4 warps x 8 n-blocks of 8 px; K=32 via predicated kb=3 ----
    {
        const int lane = tid & 31;
        const int warp = tid >> 5;        // 0..3
        const int tig  = lane & 3;
        const int gid  = lane >> 2;       // 0..7

        // A fragments (k-major weights)
        uint32_t ah[4][4], al[4][4];
        #pragma unroll
        for (int kb = 0; kb < 4; kb++) {
            const int kc0 = kb * 8 + tig;
            const int kc1 = kc0 + 4;
            ah[kb][0] = __float_as_uint(Wth[kc0 * 16 + gid]);
            ah[kb][1] = __float_as_uint(Wth[kc0 * 16 + gid + 8]);
            ah[kb][2] = __float_as_uint(Wth[kc1 * 16 + gid]);
            ah[kb][3] = __float_as_uint(Wth[kc1 * 16 + gid + 8]);
            al[kb][0] = __float_as_uint(Wtl[kc0 * 16 + gid]);
            al[kb][1] = __float_as_uint(Wtl[kc0 * 16 + gid + 8]);
            al[kb][2] = __float_as_uint(Wtl[kc1 * 16 + gid]);
            al[kb][3] = __float_as_uint(Wtl[kc1 * 16 + gid + 8]);
        }

        #pragma unroll
        for (int j = 0; j < 8; j++) {
            const int n0 = (warp * 8 + j) * 8;   // 0..248
            const int sc = scol(n0 + gid);
            float ch[4] = {0.f, 0.f, 0.f, 0.f};  // Wh*Sh
            float cm[4] = {0.f, 0.f, 0.f, 0.f};  // Wh*Sl
            float cl[4] = {0.f, 0.f, 0.f, 0.f};  // Wl*Sh
            #pragma unroll
            for (int kb = 0; kb < 3; kb++) {
                const float s0 = S[(kb * 8 + tig) * SPITCH + sc];
                const float s1 = S[(kb * 8 + tig + 4) * SPITCH + sc];
                const float h0 = tf32_rna(s0);
                const float h1 = tf32_rna(s1);
                const uint32_t b0h = __float_as_uint(h0);
                const uint32_t b1h = __float_as_uint(h1);
                const uint32_t b0l = __float_as_uint(s0 - h0);
                const uint32_t b1l = __float_as_uint(s1 - h1);
                mma_tf32(ch, ah[kb][0], ah[kb][1], ah[kb][2], ah[kb][3], b0h, b1h);
                mma_tf32(cm, ah[kb][0], ah[kb][1], ah[kb][2], ah[kb][3], b0l, b1l);
                mma_tf32(cl, al[kb][0], al[kb][1], al[kb][2], al[kb][3], b0h, b1h);
            }
            {   // kb = 3: rows 24+tig (valid if tig<3), rows 28+tig all zero
                const float s0 = (tig < 3) ? S[(24 + tig) * SPITCH + sc] : 0.0f;
                const float h0 = tf32_rna(s0);
                const uint32_t b0h = __float_as_uint(h0);
                const uint32_t b0l = __float_as_uint(s0 - h0);
                mma_tf32(ch, ah[3][0], ah[3][1], ah[3][2], ah[3][3], b0h, 0u);
                mma_tf32(cm, ah[3][0], ah[3][1], ah[3][2], ah[3][3], b0l, 0u);
                mma_tf32(cl, al[3][0], al[3][1], al[3][2], al[3][3], b0h, 0u);
            }
            const float c0 = ch[0] + cm[0] + cl[0];
            const float c1 = ch[1] + cm[1] + cl[1];
            const float c2 = ch[2] + cm[2] + cl[2];
            const float c3 = ch[3] + cm[3] + cl[3];

            // store: px pair (n0+2*tig, +1) same output row
            const int px0 = n0 + 2 * tig;
            const int gy = tile_y + (px0 >> 4);
            const int gx = tile_x + (px0 & 15);
            float* base = out + (size_t)(b * 48 + g * 16 + gid) * (Hdim * Wdim)
                              + gy * Wdim + gx;
            *reinterpret_cast<float2*>(base) = make_float2(c0, c1);
            *reinterpret_cast<float2*>(base + (size_t)8 * Hdim * Wdim) = make_float2(c2, c3);
        }
    }
}

extern "C" void kernel_launch(void* const* d_in, const int* in_sizes, int n_in,
                              void* d_out, int out_size)
{
    const float* input  = (const float*)d_in[0];
    const float* weight = (const float*)d_in[1];
    const float* offset = (const float*)d_in[2];
    float* out = (float*)d_out;

    dim3 grid(Wdim / TX, Hdim / TY, 48);   // 10 x 10 x 48
    dcn_kernel<<<grid, THREADS, SMEM_BYTES>>>(input, weight, offset, out);
}

// round 17
// speedup vs baseline: 2.1388x; 1.1102x over previous
#include <cuda_runtime.h>
#include <cuda_fp16.h>
#include <cstdint>

// DCNv2 (R15, third submission; R15/R16 both hit broker GPUAcquisitionTimeout
// before launch): split-fp16 tensor-core einsum.
// out[16, px] = W[16x27] @ S[27, px] per (b,g). Sampling 2 px/thread with
// shared corner rows (validated R11 code). Einsum: mma.sync.m16n8k16.f16
// with 3-term split (Wh*Sh + Wh*Sl + Wl*Sh; dropped Wl*Sl ~ 2^-22).
// S stored as f16x2 tap-pairs, hi+lo planes; all cvt off the MMA path.
// CTA = 16x16 px, 128 threads, 40.7KB smem (no attribute call), 5 CTAs/SM.

namespace {
constexpr int Hdim = 160;
constexpr int Wdim = 160;
constexpr int TX = 16;
constexpr int TY = 16;
constexpr int HALO = 5;                  // shifts provably in [-4,4], +1 corner
constexpr int SMW = TX + 2 * HALO;       // 26
constexpr int SMH = TY + 2 * HALO;       // 26
constexpr int THREADS = 128;
constexpr int SP = 264;                  // S pitch in u32; 264 % 32 == 8
constexpr int AP = 24;                   // weight pair-row pitch (u32)
// smem layout (bytes)
constexpr int SH_OFF = 0;                           // u32[14][SP] hi plane
constexpr int SL_OFF = SH_OFF + 14 * SP * 4;        // u32[14][SP] lo plane
constexpr int AH_OFF = SL_OFF + 14 * SP * 4;        // u32[16][AP]
constexpr int AL_OFF = AH_OFF + 16 * AP * 4;
constexpr int IN_OFF = AL_OFF + 16 * AP * 4;        // f32[3][SMH][SMW]
constexpr int SMEM_BYTES = IN_OFF + 3 * SMH * SMW * 4;   // 40752 < 48KB
}

__device__ __forceinline__ void mma_f16(float* c,
                                        uint32_t a0, uint32_t a1, uint32_t a2, uint32_t a3,
                                        uint32_t b0, uint32_t b1) {
    asm("mma.sync.aligned.m16n8k16.row.col.f32.f16.f16.f32 "
        "{%0,%1,%2,%3}, {%4,%5,%6,%7}, {%8,%9}, {%0,%1,%2,%3};"
        : "+f"(c[0]), "+f"(c[1]), "+f"(c[2]), "+f"(c[3])
        : "r"(a0), "r"(a1), "r"(a2), "r"(a3), "r"(b0), "r"(b1));
}

// split a float pair into f16x2 hi + f16x2 lo (lo = exact residual, f16-rounded)
__device__ __forceinline__ void split_pair(float a, float b, uint32_t& hi, uint32_t& lo) {
    __half2 h = __floats2half2_rn(a, b);        // .x = a (low half = even tap)
    float2 f = __half22float2(h);
    __half2 l = __floats2half2_rn(a - f.x, b - f.y);
    hi = *reinterpret_cast<uint32_t*>(&h);
    lo = *reinterpret_cast<uint32_t*>(&l);
}

// XOR-16 swizzle on the S column index (bit5 -> flip bit4)
__device__ __forceinline__ int scol(int px) {
    return px ^ (((px >> 5) & 1) << 4);
}

__global__ __launch_bounds__(THREADS, 5)
void dcn_kernel(const float* __restrict__ input,
                const float* __restrict__ weight,
                const float* __restrict__ offset,
                float* __restrict__ out)
{
    extern __shared__ char dsm[];
    uint32_t* SH  = reinterpret_cast<uint32_t*>(dsm + SH_OFF);  // [14][SP]
    uint32_t* SL  = reinterpret_cast<uint32_t*>(dsm + SL_OFF);  // [14][SP]
    uint32_t* AH  = reinterpret_cast<uint32_t*>(dsm + AH_OFF);  // [16][AP]
    uint32_t* AL  = reinterpret_cast<uint32_t*>(dsm + AL_OFF);  // [16][AP]
    float*   smin = reinterpret_cast<float*>(dsm + IN_OFF);     // [3][SMH][SMW]

    const int bg = blockIdx.z;          // 0..47
    const int b  = bg / 3;
    const int g  = bg % 3;
    const int tile_x = blockIdx.x * TX;
    const int tile_y = blockIdx.y * TY;
    const int tid = threadIdx.x;

    // ---- phase 0: weights -> pair-row f16x2 hi/lo planes ----
    // At[r][o] = pack(W[o][2r], W[o][2r+1]); taps >= 27 are zero.
    for (int i = tid; i < 16 * 16; i += THREADS) {
        const int r = i >> 4;           // pair row 0..15 (taps 2r, 2r+1)
        const int o = i & 15;
        float w0 = 0.0f, w1 = 0.0f;
        const int k0 = 2 * r, k1 = 2 * r + 1;
        if (k0 < 27) w0 = weight[(k0 % 9) * 144 + (g * 16 + o) * 3 + (k0 / 9)];
        if (k1 < 27) w1 = weight[(k1 % 9) * 144 + (g * 16 + o) * 3 + (k1 / 9)];
        uint32_t hi, lo;
        split_pair(w0, w1, hi, lo);
        AH[r * AP + o] = hi;
        AL[r * AP + o] = lo;
    }
    // stage input tile (+halo, zero pad outside image)
    const float* inb = input + (size_t)(b >> 1) * 9 * Hdim * Wdim
                             + (size_t)(g * 3) * Hdim * Wdim;
    for (int i = tid; i < 3 * SMH * SMW; i += THREADS) {
        const int c = i / (SMH * SMW);
        const int r = (i / SMW) % SMH;
        const int q = i % SMW;
        const int gy = tile_y + r - HALO;
        const int gx = tile_x + q - HALO;
        float v = 0.0f;
        if (gy >= 0 && gy < Hdim && gx >= 0 && gx < Wdim)
            v = inb[(size_t)c * Hdim * Wdim + gy * Wdim + gx];
        smin[i] = v;
    }

    // ---- shift constants (uniform across block) ----
    const float offy = __ldg(&offset[(b * 3 + g) * 2 + 0]);
    const float offx = __ldg(&offset[(b * 3 + g) * 2 + 1]);
    const float dyv = 1.0f + 3.0f / offy;   // |shift| for p = +-1; p=0 -> 0
    const float dxv = 1.0f + 3.0f / offx;
    const float fyMf = floorf(-dyv), fyPf = floorf(dyv);
    const float fxMf = floorf(-dxv), fxPf = floorf(dxv);
    const int fyM = (int)fyMf, fyP = (int)fyPf;
    const int fxM = (int)fxMf, fxP = (int)fxPf;
    const float wyM = -dyv - fyMf, wyP = dyv - fyPf;
    const float wxM = -dxv - fxMf, wxP = dxv - fxPf;

    __syncthreads();

    // ---- phase 1: sampling 2 px/thread, then pack tap-pairs to hi/lo ----
    {
        const int x  = tid & 15;
        const int yh = tid >> 4;          // 0..7
        const int y0 = yh * 2;
        const int sc0 = scol(y0 * 16 + x);
        const int sc1 = scol(y0 * 16 + 16 + x);

        float s0[27], s1[27];             // statically indexed (unrolled below)
        #pragma unroll
        for (int c = 0; c < 3; c++) {
            const float* Bc = smin + c * (SMH * SMW) + (y0 + HALO) * SMW + (x + HALO);
            const float* BM = Bc + fyM * SMW;   // p_y=-1 rows
            const float* BP = Bc + fyP * SMW;   // p_y=+1 rows

            #define HL(P, FX, WX) (fmaf((WX), (P)[(FX) + 1] - (P)[(FX)], (P)[(FX)]))
            #define VL(A, B2, W)  (fmaf((W), (B2) - (A), (A)))

            // p_y = 0
            s0[c * 9 + 4] = Bc[0];               s1[c * 9 + 4] = Bc[SMW];
            s0[c * 9 + 3] = HL(Bc, fxM, wxM);    s1[c * 9 + 3] = HL(Bc + SMW, fxM, wxM);
            s0[c * 9 + 5] = HL(Bc, fxP, wxP);    s1[c * 9 + 5] = HL(Bc + SMW, fxP, wxP);
            // p_y = -1 (3 shared rows for 2 px)
            {
                float v0 = BM[0], v1 = BM[SMW], v2 = BM[2 * SMW];
                s0[c * 9 + 1] = VL(v0, v1, wyM); s1[c * 9 + 1] = VL(v1, v2, wyM);
                float h0 = HL(BM, fxM, wxM), h1 = HL(BM + SMW, fxM, wxM),
                      h2 = HL(BM + 2 * SMW, fxM, wxM);
                s0[c * 9 + 0] = VL(h0, h1, wyM); s1[c * 9 + 0] = VL(h1, h2, wyM);
                float e0 = HL(BM, fxP, wxP), e1 = HL(BM + SMW, fxP, wxP),
                      e2 = HL(BM + 2 * SMW, fxP, wxP);
                s0[c * 9 + 2] = VL(e0, e1, wyM); s1[c * 9 + 2] = VL(e1, e2, wyM);
            }
            // p_y = +1
            {
                float v0 = BP[0], v1 = BP[SMW], v2 = BP[2 * SMW];
                s0[c * 9 + 7] = VL(v0, v1, wyP); s1[c * 9 + 7] = VL(v1, v2, wyP);
                float h0 = HL(BP, fxM, wxM), h1 = HL(BP + SMW, fxM, wxM),
                      h2 = HL(BP + 2 * SMW, fxM, wxM);
                s0[c * 9 + 6] = VL(h0, h1, wyP); s1[c * 9 + 6] = VL(h1, h2, wyP);
                float e0 = HL(BP, fxP, wxP), e1 = HL(BP + SMW, fxP, wxP),
                      e2 = HL(BP + 2 * SMW, fxP, wxP);
                s0[c * 9 + 8] = VL(e0, e1, wyP); s1[c * 9 + 8] = VL(e1, e2, wyP);
            }
            #undef HL
            #undef VL
        }
        // pack tap-pairs (2r, 2r+1); row 13 = (tap26, 0)
        #pragma unroll
        for (int r = 0; r < 14; r++) {
            const float a0 = s0[2 * r];
            const float b0v = (2 * r + 1 < 27) ? s0[2 * r + 1] : 0.0f;
            const float a1 = s1[2 * r];
            const float b1v = (2 * r + 1 < 27) ? s1[2 * r + 1] : 0.0f;
            uint32_t hi, lo;
            split_pair(a0, b0v, hi, lo);
            SH[r * SP + sc0] = hi;  SL[r * SP + sc0] = lo;
            split_pair(a1, b1v, hi, lo);
            SH[r * SP + sc1] = hi;  SL[r * SP + sc1] = lo;
        }
    }

    __syncthreads();

    // ---- phase 2: MMA. 4 warps x 8 n-blocks of 8 px; K=32 via 2 k16 steps ----
    {
        const int lane = tid & 31;
        const int warp = tid >> 5;        // 0..3
        const int tig  = lane & 3;
        const int gid  = lane >> 2;       // 0..7

        // A fragments: kb=0 rows (tig, tig+4); kb=1 rows (8+tig, 12+tig)
        uint32_t ah[2][4], al[2][4];
        #pragma unroll
        for (int kb = 0; kb < 2; kb++) {
            const int r0 = kb * 8 + tig;
            const int r1 = r0 + 4;
            ah[kb][0] = AH[r0 * AP + gid];
            ah[kb][1] = AH[r0 * AP + gid + 8];
            ah[kb][2] = AH[r1 * AP + gid];
            ah[kb][3] = AH[r1 * AP + gid + 8];
            al[kb][0] = AL[r0 * AP + gid];
            al[kb][1] = AL[r0 * AP + gid + 8];
            al[kb][2] = AL[r1 * AP + gid];
            al[kb][3] = AL[r1 * AP + gid + 8];
        }

        #pragma unroll 4
        for (int j = 0; j < 8; j++) {
            const int n0 = (warp * 8 + j) * 8;   // 0..248
            const int sc = scol(n0 + gid);
            float cm[4] = {0.f, 0.f, 0.f, 0.f};  // main: Wh*Sh
            float cc[4] = {0.f, 0.f, 0.f, 0.f};  // corr: Wh*Sl + Wl*Sh
            // kb = 0: S pair-rows (tig, tig+4)
            {
                const uint32_t bh0 = SH[tig * SP + sc];
                const uint32_t bh1 = SH[(tig + 4) * SP + sc];
                const uint32_t bl0 = SL[tig * SP + sc];
                const uint32_t bl1 = SL[(tig + 4) * SP + sc];
                mma_f16(cm, ah[0][0], ah[0][1], ah[0][2], ah[0][3], bh0, bh1);
                mma_f16(cc, ah[0][0], ah[0][1], ah[0][2], ah[0][3], bl0, bl1);
                mma_f16(cc, al[0][0], al[0][1], al[0][2], al[0][3], bh0, bh1);
            }
            // kb = 1: S pair-rows (8+tig, 12+tig); rows 14,15 (taps 28..31) = 0
            {
                const uint32_t bh0 = SH[(8 + tig) * SP + sc];
                const uint32_t bh1 = (tig < 2) ? SH[(12 + tig) * SP + sc] : 0u;
                const uint32_t bl0 = SL[(8 + tig) * SP + sc];
                const uint32_t bl1 = (tig < 2) ? SL[(12 + tig) * SP + sc] : 0u;
                mma_f16(cm, ah[1][0], ah[1][1], ah[1][2], ah[1][3], bh0, bh1);
                mma_f16(cc, ah[1][0], ah[1][1], ah[1][2], ah[1][3], bl0, bl1);
                mma_f16(cc, al[1][0], al[1][1], al[1][2], al[1][3], bh0, bh1);
            }
            const float c0 = cm[0] + cc[0];
            const float c1 = cm[1] + cc[1];
            const float c2 = cm[2] + cc[2];
            const float c3 = cm[3] + cc[3];

            // store: px pair (n0+2*tig, +1) same output row
            const int px0 = n0 + 2 * tig;
            const int gy = tile_y + (px0 >> 4);
            const int gx = tile_x + (px0 & 15);
            float* base = out + (size_t)(b * 48 + g * 16 + gid) * (Hdim * Wdim)
                              + gy * Wdim + gx;
            *reinterpret_cast<float2*>(base) = make_float2(c0, c1);
            *reinterpret_cast<float2*>(base + (size_t)8 * Hdim * Wdim) = make_float2(c2, c3);
        }
    }
}

extern "C" void kernel_launch(void* const* d_in, const int* in_sizes, int n_in,
                              void* d_out, int out_size)
{
    const float* input  = (const float*)d_in[0];
    const float* weight = (const float*)d_in[1];
    const float* offset = (const float*)d_in[2];
    float* out = (float*)d_out;

    dim3 grid(Wdim / TX, Hdim / TY, 48);   // 10 x 10 x 48
    dcn_kernel<<<grid, THREADS, SMEM_BYTES>>>(input, weight, offset, out);
}